// round 1
// baseline (speedup 1.0000x reference)
#include <cuda_runtime.h>
#include <math.h>

// Problem constants
constexpr int Hh  = 8;
constexpr int Dh  = 32;
constexpr int Jn  = 22;
constexpr int Sn  = 66;
constexpr int INn = 256;
#define NEGV (-9e15f)

// Shared memory layout (floats)
constexpr int XS_STRIDE  = 257;   // 66 x 257   (row+k conflict-free)
constexpr int WS_STRIDE  = 98;    // 256 x 98   (96 used; 8B-aligned pairs)
constexpr int QKV_STRIDE = 101;   // 66 x 101   (q:0-31, k:32-63, v:64-95)
constexpr int P_STRIDE   = 67;    // 66 x 67
constexpr int O_STRIDE   = 33;    // 66 x 33
constexpr int XS_OFF  = 0;
constexpr int WS_OFF  = XS_OFF  + Sn * XS_STRIDE;    // 16962
constexpr int QKV_OFF = WS_OFF  + 256 * WS_STRIDE;   // 42050
constexpr int P_OFF   = QKV_OFF + Sn * QKV_STRIDE;   // 48716
constexpr int O_OFF   = P_OFF   + Sn * P_STRIDE;     // 53138
constexpr int WC_OFF  = O_OFF   + Sn * O_STRIDE;     // 55316
constexpr int SMEM_FLOATS = WC_OFF + Jn * Sn;        // 56768 -> 227072 bytes

// ---- packed f32x2 helpers (ptxas never emits FFMA2 from C++) ----
static __device__ __forceinline__ unsigned long long pk2(float a, float b) {
    unsigned long long r;
    asm("mov.b64 %0, {%1,%2};" : "=l"(r) : "f"(a), "f"(b));
    return r;
}
static __device__ __forceinline__ void upk2(unsigned long long v, float &a, float &b) {
    asm("mov.b64 {%0,%1}, %2;" : "=f"(a), "=f"(b) : "l"(v));
}
static __device__ __forceinline__ unsigned long long ffma2(unsigned long long a,
                                                           unsigned long long b,
                                                           unsigned long long c) {
    unsigned long long d;
    asm("fma.rn.f32x2 %0, %1, %2, %3;" : "=l"(d) : "l"(a), "l"(b), "l"(c));
    return d;
}

__global__ __launch_bounds__(256, 1)
void mha_fused_kernel(const float* __restrict__ x,
                      const float* __restrict__ Wq, const float* __restrict__ bq,
                      const float* __restrict__ Wk, const float* __restrict__ bk,
                      const float* __restrict__ Wv, const float* __restrict__ bv,
                      const float* __restrict__ Wc, const float* __restrict__ bc,
                      float* __restrict__ out)
{
    extern __shared__ float sm[];
    float* xs  = sm + XS_OFF;
    float* ws  = sm + WS_OFF;
    float* qkv = sm + QKV_OFF;
    float* pp  = sm + P_OFF;
    float* oo  = sm + O_OFF;
    float* wcs = sm + WC_OFF;

    const int bt  = blockIdx.x;   // b*T + t
    const int tid = threadIdx.x;

    // ---- stage x tile (66 x 256), coalesced ----
    const float* xg = x + (size_t)bt * (Sn * INn);
    for (int idx = tid; idx < Sn * INn; idx += 256) {
        int s = idx >> 8, c = idx & 255;
        xs[s * XS_STRIDE + c] = xg[idx];
    }
    // ---- stage Wc (22 x 66) ----
    for (int idx = tid; idx < Jn * Sn; idx += 256) wcs[idx] = Wc[idx];
    __syncthreads();

    const int tm = tid & 15;       // row group
    const int tn = tid >> 4;       // col group
    const int n0 = tn * 6;         // output cols n0..n0+5 of 96
    const bool row4_valid = (tm < 2);
    // row for u=4: alias to row tm when invalid (accumulator discarded)
    int rowu4 = row4_valid ? (tm + 64) : tm;

    for (int h = 0; h < Hh; ++h) {
        // ---- stage weight slice ws[k][n]; n<32: Wq, <64: Wk, <96: Wv ----
        for (int it = 0; it < 96; ++it) {
            int n = it;
            const float* Wsrc = (n < 32) ? Wq : (n < 64 ? Wk : Wv);
            float v = Wsrc[(h * 32 + (n & 31)) * 256 + tid];
            ws[tid * WS_STRIDE + n] = v;
        }
        __syncthreads();

        // ---- QKV projection: C[66][96] = xs[66][256] @ ws[256][96] ----
        unsigned long long acc[5][3];
        #pragma unroll
        for (int u = 0; u < 5; ++u)
            #pragma unroll
            for (int j = 0; j < 3; ++j) acc[u][j] = 0ULL;

        const float* xr0 = xs + (tm +  0) * XS_STRIDE;
        const float* xr1 = xs + (tm + 16) * XS_STRIDE;
        const float* xr2 = xs + (tm + 32) * XS_STRIDE;
        const float* xr3 = xs + (tm + 48) * XS_STRIDE;
        const float* xr4 = xs + rowu4     * XS_STRIDE;

        #pragma unroll 2
        for (int k = 0; k < 256; ++k) {
            const float* wrow = ws + k * WS_STRIDE + n0;
            unsigned long long b0 = *(const unsigned long long*)(wrow);
            unsigned long long b1 = *(const unsigned long long*)(wrow + 2);
            unsigned long long b2 = *(const unsigned long long*)(wrow + 4);
            unsigned long long a0 = pk2(xr0[k], xr0[k]);
            unsigned long long a1 = pk2(xr1[k], xr1[k]);
            unsigned long long a2 = pk2(xr2[k], xr2[k]);
            unsigned long long a3 = pk2(xr3[k], xr3[k]);
            unsigned long long a4 = pk2(xr4[k], xr4[k]);
            acc[0][0] = ffma2(a0, b0, acc[0][0]);
            acc[0][1] = ffma2(a0, b1, acc[0][1]);
            acc[0][2] = ffma2(a0, b2, acc[0][2]);
            acc[1][0] = ffma2(a1, b0, acc[1][0]);
            acc[1][1] = ffma2(a1, b1, acc[1][1]);
            acc[1][2] = ffma2(a1, b2, acc[1][2]);
            acc[2][0] = ffma2(a2, b0, acc[2][0]);
            acc[2][1] = ffma2(a2, b1, acc[2][1]);
            acc[2][2] = ffma2(a2, b2, acc[2][2]);
            acc[3][0] = ffma2(a3, b0, acc[3][0]);
            acc[3][1] = ffma2(a3, b1, acc[3][1]);
            acc[3][2] = ffma2(a3, b2, acc[3][2]);
            acc[4][0] = ffma2(a4, b0, acc[4][0]);
            acc[4][1] = ffma2(a4, b1, acc[4][1]);
            acc[4][2] = ffma2(a4, b2, acc[4][2]);
        }

        // biases for the 6 output columns of this thread
        float bias[6];
        #pragma unroll
        for (int j = 0; j < 6; ++j) {
            int n = n0 + j;
            const float* bsrc = (n < 32) ? bq : (n < 64 ? bk : bv);
            bias[j] = bsrc[h * 32 + (n & 31)];
        }

        // write q|k|v to smem (relu on v)
        #pragma unroll
        for (int u = 0; u < 5; ++u) {
            if (u == 4 && !row4_valid) break;
            int r = (u == 4) ? (tm + 64) : (tm + 16 * u);
            #pragma unroll
            for (int jp = 0; jp < 3; ++jp) {
                float vlo, vhi;
                upk2(acc[u][jp], vlo, vhi);
                int n = n0 + 2 * jp;
                float o0 = vlo + bias[2 * jp];
                float o1 = vhi + bias[2 * jp + 1];
                if (n     >= 64) o0 = fmaxf(o0, 0.0f);
                if (n + 1 >= 64) o1 = fmaxf(o1, 0.0f);
                qkv[r * QKV_STRIDE + n]     = o0;
                qkv[r * QKV_STRIDE + n + 1] = o1;
            }
        }
        __syncthreads();

        // ---- scores (masked, scaled) into pp ----
        const float scale = 0.17677669529663687f;  // 1/sqrt(32)
        for (int idx = tid; idx < Sn * Sn; idx += 256) {
            int i  = idx / Sn;
            int jj = idx - i * Sn;
            bool masked = (i < Jn && jj >= 2 * Jn) || (i >= 2 * Jn && jj < Jn);
            float s = 0.0f;
            if (!masked) {
                const float* qi = qkv + i  * QKV_STRIDE;
                const float* kj = qkv + jj * QKV_STRIDE + 32;
                float d0 = 0.0f;
                #pragma unroll 8
                for (int dd = 0; dd < 32; ++dd) d0 += qi[dd] * kj[dd];
                s = d0 * scale;
            }
            pp[i * P_STRIDE + jj] = s;
        }
        __syncthreads();

        // ---- per-row: max, |s|<=m/9 prune, softmax ----
        if (tid < Sn) {
            float* row = pp + tid * P_STRIDE;
            float m = row[0];
            for (int jj = 1; jj < Sn; ++jj) m = fmaxf(m, row[jj]);
            float thr = m * (1.0f / 9.0f);
            float M2 = -3.402823466e38f;
            for (int jj = 0; jj < Sn; ++jj) {
                float sV = row[jj];
                float ts = (fabsf(sV) <= thr) ? NEGV : sV;
                row[jj] = ts;
                M2 = fmaxf(M2, ts);
            }
            float sum = 0.0f;
            for (int jj = 0; jj < Sn; ++jj) {
                float e = __expf(row[jj] - M2);
                row[jj] = e;
                sum += e;
            }
            float inv = 1.0f / sum;
            for (int jj = 0; jj < Sn; ++jj) row[jj] *= inv;
        }
        __syncthreads();

        // ---- out = P @ V  (66 x 32) ----
        for (int idx = tid; idx < Sn * Dh; idx += 256) {
            int i  = idx >> 5;
            int dd = idx & 31;
            const float* pr = pp + i * P_STRIDE;
            const float* vv = qkv + 64 + dd;
            float a = 0.0f;
            #pragma unroll 6
            for (int c = 0; c < Sn; ++c) a += pr[c] * vv[c * QKV_STRIDE];
            oo[i * O_STRIDE + dd] = a;
        }
        __syncthreads();

        // ---- classifier over S axis: y[j][d] = bc[j] + sum_s Wc[j][s]*o[s][d] ----
        const size_t obase = (size_t)bt * (Jn * 256) + (size_t)h * 32;
        for (int idx = tid; idx < Jn * Dh; idx += 256) {
            int j  = idx >> 5;
            int dd = idx & 31;
            const float* wr = wcs + j * Sn;
            float a = bc[j];
            #pragma unroll 6
            for (int c = 0; c < Sn; ++c) a += wr[c] * oo[c * O_STRIDE + dd];
            out[obase + (size_t)j * 256 + dd] = a;
        }
        __syncthreads();
    }
}

extern "C" void kernel_launch(void* const* d_in, const int* in_sizes, int n_in,
                              void* d_out, int out_size) {
    const float* x  = (const float*)d_in[0];
    const float* Wq = (const float*)d_in[1];
    const float* bq = (const float*)d_in[2];
    const float* Wk = (const float*)d_in[3];
    const float* bk = (const float*)d_in[4];
    const float* Wv = (const float*)d_in[5];
    const float* bv = (const float*)d_in[6];
    const float* Wc = (const float*)d_in[7];
    const float* bc = (const float*)d_in[8];
    float* out = (float*)d_out;

    int blocks = in_sizes[0] / (Sn * INn);   // B*T = 3072
    size_t smem = (size_t)SMEM_FLOATS * sizeof(float);  // 227072 bytes
    cudaFuncSetAttribute(mha_fused_kernel,
                         cudaFuncAttributeMaxDynamicSharedMemorySize, (int)smem);
    mha_fused_kernel<<<blocks, 256, smem>>>(x, Wq, bq, Wk, bk, Wv, bv, Wc, bc, out);
}

// round 2
// speedup vs baseline: 1.3737x; 1.3737x over previous
#include <cuda_runtime.h>
#include <math.h>
#include <float.h>

constexpr int Hh  = 8;
constexpr int Jn  = 22;
constexpr int Sn  = 66;
#define NEGV (-9e15f)

// Shared layout (floats)
constexpr int XS_STRIDE = 257;  // 66 x 257  (odd: conflict-free column reads)
constexpr int WS_STRIDE = 98;   // 256 x 98  (even: 8B-aligned pairs)
constexpr int QS_STRIDE = 37;   // 66 x 37   (q row-major; 5r+d conflict-free)
constexpr int KT_STRIDE = 70;   // 32 x 70   (k transposed; even for LDS.64)
constexpr int VS_STRIDE = 34;   // 66 x 34   (v row-major; even for LDS.64)
constexpr int P_STRIDE  = 67;   // 66 x 67   (odd: conflict-free column reads)
constexpr int O_STRIDE  = 33;   // 66 x 33
constexpr int WC_STRIDE = 67;   // 22 x 67

constexpr int XS_OFF = 0;
constexpr int WS_OFF = XS_OFF + Sn * XS_STRIDE;          // 16962
constexpr int QS_OFF = WS_OFF + 256 * WS_STRIDE;         // 42050
constexpr int KT_OFF = QS_OFF + Sn * QS_STRIDE;          // 44492
constexpr int VS_OFF = KT_OFF + 32 * KT_STRIDE;          // 46732
constexpr int PP_OFF = VS_OFF + Sn * VS_STRIDE;          // 48976
constexpr int OO_OFF = PP_OFF + Sn * P_STRIDE;           // 53398
constexpr int WC_OFF = OO_OFF + Sn * O_STRIDE;           // 55576
constexpr int SMEM_FLOATS = WC_OFF + Jn * WC_STRIDE;     // 57050 -> 228200 B

typedef unsigned long long ull;

static __device__ __forceinline__ ull pk2(float a, float b) {
    ull r; asm("mov.b64 %0, {%1,%2};" : "=l"(r) : "f"(a), "f"(b)); return r;
}
static __device__ __forceinline__ void upk2(ull v, float &a, float &b) {
    asm("mov.b64 {%0,%1}, %2;" : "=f"(a), "=f"(b) : "l"(v));
}
static __device__ __forceinline__ ull ffma2(ull a, ull b, ull c) {
    ull d; asm("fma.rn.f32x2 %0, %1, %2, %3;" : "=l"(d) : "l"(a), "l"(b), "l"(c)); return d;
}

__global__ __launch_bounds__(512, 1)
void mha_fused_kernel(const float* __restrict__ x,
                      const float* __restrict__ Wq, const float* __restrict__ bq,
                      const float* __restrict__ Wk, const float* __restrict__ bk,
                      const float* __restrict__ Wv, const float* __restrict__ bv,
                      const float* __restrict__ Wc, const float* __restrict__ bc,
                      float* __restrict__ out)
{
    extern __shared__ float sm[];
    float* xs  = sm + XS_OFF;
    float* ws  = sm + WS_OFF;
    float* qs  = sm + QS_OFF;
    float* kt  = sm + KT_OFF;
    float* vs  = sm + VS_OFF;
    float* pp  = sm + PP_OFF;
    float* oo  = sm + OO_OFF;
    float* wcs = sm + WC_OFF;

    const int bt  = blockIdx.x;
    const int tid = threadIdx.x;
    const int lane = tid & 31;
    const int wid  = tid >> 5;

    // ---- stage x tile (66 x 256), coalesced ----
    const float* xg = x + (size_t)bt * (Sn * 256);
    for (int idx = tid; idx < Sn * 256; idx += 512) {
        int s = idx >> 8, c = idx & 255;
        xs[s * XS_STRIDE + c] = xg[idx];
    }
    for (int idx = tid; idx < Jn * Sn; idx += 512) {
        int j = idx / Sn, c = idx - j * Sn;
        wcs[j * WC_STRIDE + c] = Wc[idx];
    }
    __syncthreads();

    // projection tiling: tm rows {tm, tm+32}, tn -> 6 cols
    const int tm = lane;           // 0..31 (tn uniform within warp)
    const int tn = wid >> 1;       // 0..7?  NO: need 16 groups
    // 512 threads = 16 warps; col group = warp id, but we need 16 groups x 6 = 96
    const int n0 = wid * 6;        // 16 warps * 6 cols = 96  ✓

    for (int h = 0; h < Hh; ++h) {
        // ---- stage weight slice ws[k][n] (n<32:Wq, <64:Wk, <96:Wv) ----
        for (int e = tid; e < 96 * 256; e += 512) {
            int n = e >> 8, k = e & 255;
            const float* Wsrc = (n < 32) ? Wq : (n < 64 ? Wk : Wv);
            ws[k * WS_STRIDE + n] = Wsrc[(h * 32 + (n & 31)) * 256 + k];
        }
        __syncthreads();

        // ---- QKV projection main GEMM: rows 0..63, all 96 cols ----
        {
            ull acc[2][3];
            #pragma unroll
            for (int u = 0; u < 2; ++u)
                #pragma unroll
                for (int j = 0; j < 3; ++j) acc[u][j] = 0ULL;

            const float* xr0 = xs + tm * XS_STRIDE;
            const float* xr1 = xs + (tm + 32) * XS_STRIDE;

            #pragma unroll 4
            for (int k = 0; k < 256; ++k) {
                const float* wrow = ws + k * WS_STRIDE + n0;
                ull b0 = *(const ull*)(wrow);
                ull b1 = *(const ull*)(wrow + 2);
                ull b2 = *(const ull*)(wrow + 4);
                float a0s = xr0[k], a1s = xr1[k];
                ull a0 = pk2(a0s, a0s);
                ull a1 = pk2(a1s, a1s);
                acc[0][0] = ffma2(a0, b0, acc[0][0]);
                acc[0][1] = ffma2(a0, b1, acc[0][1]);
                acc[0][2] = ffma2(a0, b2, acc[0][2]);
                acc[1][0] = ffma2(a1, b0, acc[1][0]);
                acc[1][1] = ffma2(a1, b1, acc[1][1]);
                acc[1][2] = ffma2(a1, b2, acc[1][2]);
            }

            float bias[6];
            #pragma unroll
            for (int j = 0; j < 6; ++j) {
                int n = n0 + j;
                const float* bsrc = (n < 32) ? bq : (n < 64 ? bk : bv);
                bias[j] = bsrc[h * 32 + (n & 31)];
            }

            #pragma unroll
            for (int u = 0; u < 2; ++u) {
                int r = tm + 32 * u;
                #pragma unroll
                for (int jp = 0; jp < 3; ++jp) {
                    float vlo, vhi;
                    upk2(acc[u][jp], vlo, vhi);
                    int n = n0 + 2 * jp;
                    float o0 = vlo + bias[2 * jp];
                    float o1 = vhi + bias[2 * jp + 1];
                    // route element 0
                    if (n < 32)       qs[r * QS_STRIDE + n] = o0;
                    else if (n < 64)  kt[(n - 32) * KT_STRIDE + r] = o0;
                    else              vs[r * VS_STRIDE + (n - 64)] = fmaxf(o0, 0.0f);
                    int n1 = n + 1;
                    if (n1 < 32)      qs[r * QS_STRIDE + n1] = o1;
                    else if (n1 < 64) kt[(n1 - 32) * KT_STRIDE + r] = o1;
                    else              vs[r * VS_STRIDE + (n1 - 64)] = fmaxf(o1, 0.0f);
                }
            }
        }

        // ---- projection cleanup: rows 64,65 (192 outputs) ----
        if (tid < 192) {
            int row = 64 + (tid >= 96);
            int n = tid - (tid >= 96 ? 96 : 0);
            const float* xr = xs + row * XS_STRIDE;
            const float* wp = ws + n;
            float a = 0.0f, b = 0.0f;
            #pragma unroll 4
            for (int k = 0; k < 256; k += 2) {
                a += xr[k]     * wp[k * WS_STRIDE];
                b += xr[k + 1] * wp[(k + 1) * WS_STRIDE];
            }
            const float* bsrc = (n < 32) ? bq : (n < 64 ? bk : bv);
            float v = a + b + bsrc[h * 32 + (n & 31)];
            if (n < 32)      qs[row * QS_STRIDE + n] = v;
            else if (n < 64) kt[(n - 32) * KT_STRIDE + row] = v;
            else             vs[row * VS_STRIDE + (n - 64)] = fmaxf(v, 0.0f);
        }
        __syncthreads();

        // ---- scores GEMM: pp[i][j] = scale * q[i]·k[j], masked -> 0 ----
        const float scale = 0.17677669529663687f; // 1/sqrt(32)
        {
            int j0 = wid * 4;  // 16 warps * 4 cols = 64 cols (64,65 in cleanup)
            ull acc[2][2] = {{0ULL, 0ULL}, {0ULL, 0ULL}};
            const float* q0 = qs + tm * QS_STRIDE;
            const float* q1 = qs + (tm + 32) * QS_STRIDE;
            #pragma unroll
            for (int d = 0; d < 32; ++d) {
                const float* krow = kt + d * KT_STRIDE + j0;
                ull b0 = *(const ull*)(krow);
                ull b1 = *(const ull*)(krow + 2);
                float a0s = q0[d], a1s = q1[d];
                ull a0 = pk2(a0s, a0s);
                ull a1 = pk2(a1s, a1s);
                acc[0][0] = ffma2(a0, b0, acc[0][0]);
                acc[0][1] = ffma2(a0, b1, acc[0][1]);
                acc[1][0] = ffma2(a1, b0, acc[1][0]);
                acc[1][1] = ffma2(a1, b1, acc[1][1]);
            }
            #pragma unroll
            for (int u = 0; u < 2; ++u) {
                int i = tm + 32 * u;
                #pragma unroll
                for (int jp = 0; jp < 2; ++jp) {
                    float s0, s1;
                    upk2(acc[u][jp], s0, s1);
                    int j = j0 + 2 * jp;
                    bool m0 = (i < Jn && j     >= 2 * Jn) || (i >= 2 * Jn && j     < Jn);
                    bool m1 = (i < Jn && j + 1 >= 2 * Jn) || (i >= 2 * Jn && j + 1 < Jn);
                    pp[i * P_STRIDE + j]     = m0 ? 0.0f : s0 * scale;
                    pp[i * P_STRIDE + j + 1] = m1 ? 0.0f : s1 * scale;
                }
            }
        }
        // scores cleanup: i>=64 (all j) plus j in {64,65} for i<64
        if (tid < 260) {
            int i, j;
            if (tid < 132) { i = 64 + tid / 66; j = tid % 66; }
            else { int t2 = tid - 132; i = t2 >> 1; j = 64 + (t2 & 1); }
            bool masked = (i < Jn && j >= 2 * Jn) || (i >= 2 * Jn && j < Jn);
            float s = 0.0f;
            if (!masked) {
                const float* qi = qs + i * QS_STRIDE;
                float d0 = 0.0f;
                #pragma unroll 8
                for (int d = 0; d < 32; ++d) d0 += qi[d] * kt[d * KT_STRIDE + j];
                s = d0 * scale;
            }
            pp[i * P_STRIDE + j] = s;
        }
        __syncthreads();

        // ---- softmax with threshold pruning: warp per row ----
        for (int r = wid; r < Sn; r += 16) {
            float* row = pp + r * P_STRIDE;
            float v0 = row[lane];
            float v1 = row[lane + 32];
            float v2 = (lane < 2) ? row[lane + 64] : -FLT_MAX;
            float m = fmaxf(fmaxf(v0, v1), v2);
            #pragma unroll
            for (int o = 16; o; o >>= 1) m = fmaxf(m, __shfl_xor_sync(0xffffffffu, m, o));
            float thr = m * (1.0f / 9.0f);
            float t0 = (fabsf(v0) <= thr) ? NEGV : v0;
            float t1 = (fabsf(v1) <= thr) ? NEGV : v1;
            float t2 = (lane < 2) ? ((fabsf(v2) <= thr) ? NEGV : v2) : -FLT_MAX;
            float M2 = fmaxf(fmaxf(t0, t1), t2);
            #pragma unroll
            for (int o = 16; o; o >>= 1) M2 = fmaxf(M2, __shfl_xor_sync(0xffffffffu, M2, o));
            float e0 = __expf(t0 - M2);
            float e1 = __expf(t1 - M2);
            float e2 = (lane < 2) ? __expf(t2 - M2) : 0.0f;
            float s = e0 + e1 + e2;
            #pragma unroll
            for (int o = 16; o; o >>= 1) s += __shfl_xor_sync(0xffffffffu, s, o);
            float inv = 1.0f / s;
            row[lane]      = e0 * inv;
            row[lane + 32] = e1 * inv;
            if (lane < 2) row[lane + 64] = e2 * inv;
        }
        __syncthreads();

        // ---- P @ V : oo[i][dd] (rows 0..63 GEMM, rows 64,65 cleanup) ----
        {
            int dd0 = wid * 2;  // 16 warps * 2 cols = 32
            ull acc0 = 0ULL, acc1 = 0ULL;
            const float* p0 = pp + tm * P_STRIDE;
            const float* p1 = pp + (tm + 32) * P_STRIDE;
            #pragma unroll 2
            for (int c = 0; c < Sn; ++c) {
                ull b = *(const ull*)(vs + c * VS_STRIDE + dd0);
                float a0s = p0[c], a1s = p1[c];
                acc0 = ffma2(pk2(a0s, a0s), b, acc0);
                acc1 = ffma2(pk2(a1s, a1s), b, acc1);
            }
            float r00, r01, r10, r11;
            upk2(acc0, r00, r01);
            upk2(acc1, r10, r11);
            oo[tm * O_STRIDE + dd0] = r00;
            oo[tm * O_STRIDE + dd0 + 1] = r01;
            oo[(tm + 32) * O_STRIDE + dd0] = r10;
            oo[(tm + 32) * O_STRIDE + dd0 + 1] = r11;
        }
        if (tid < 64) {
            int row = 64 + (tid >= 32);
            int dd = tid & 31;
            const float* pr = pp + row * P_STRIDE;
            float a = 0.0f;
            #pragma unroll 6
            for (int c = 0; c < Sn; ++c) a += pr[c] * vs[c * VS_STRIDE + dd];
            oo[row * O_STRIDE + dd] = a;
        }
        __syncthreads();

        // ---- classifier: y[j][dd] = bc[j] + sum_c Wc[j][c] * oo[c][dd] ----
        const size_t obase = (size_t)bt * (Jn * 256) + (size_t)h * 32;
        for (int t = tid; t < Jn * 32; t += 512) {
            int j = t >> 5, dd = t & 31;
            const float* wr = wcs + j * WC_STRIDE;
            float a = bc[j];
            #pragma unroll 6
            for (int c = 0; c < Sn; ++c) a += wr[c] * oo[c * O_STRIDE + dd];
            out[obase + (size_t)j * 256 + dd] = a;
        }
        __syncthreads();
    }
}

extern "C" void kernel_launch(void* const* d_in, const int* in_sizes, int n_in,
                              void* d_out, int out_size) {
    const float* x  = (const float*)d_in[0];
    const float* Wq = (const float*)d_in[1];
    const float* bq = (const float*)d_in[2];
    const float* Wk = (const float*)d_in[3];
    const float* bk = (const float*)d_in[4];
    const float* Wv = (const float*)d_in[5];
    const float* bv = (const float*)d_in[6];
    const float* Wc = (const float*)d_in[7];
    const float* bc = (const float*)d_in[8];
    float* out = (float*)d_out;

    int blocks = in_sizes[0] / (Sn * 256);   // B*T = 3072
    size_t smem = (size_t)SMEM_FLOATS * sizeof(float);
    cudaFuncSetAttribute(mha_fused_kernel,
                         cudaFuncAttributeMaxDynamicSharedMemorySize, (int)smem);
    mha_fused_kernel<<<blocks, 512, smem>>>(x, Wq, bq, Wk, bk, Wv, bv, Wc, bc, out);
}

// round 3
// speedup vs baseline: 1.7296x; 1.2591x over previous
#include <cuda_runtime.h>
#include <math.h>
#include <float.h>

constexpr int Hh = 8;
constexpr int Jn = 22;
constexpr int Sn = 66;
#define NEGV (-9e15f)

// smem strides (floats)
constexpr int XS_STRIDE  = 260;  // 66 rows
constexpr int WS2_STRIDE = 516;  // 48 pair-rows (256 float2 + pad); 2064B, 16B-mult
constexpr int QS_STRIDE  = 36;   // 66 rows
constexpr int KT_STRIDE  = 68;   // 32 rows (k transposed)
constexpr int VS_STRIDE  = 34;   // 68 rows (2 zero pad rows)
constexpr int PP_STRIDE  = 68;   // 66 rows (2 zero pad cols)
constexpr int OO_STRIDE  = 33;   // 68 rows (2 zero pad rows)
constexpr int WC_STRIDE  = 68;   // 22 rows (2 zero pad cols)

constexpr int XS_OFF  = 0;
constexpr int WS2_OFF = XS_OFF  + 66 * XS_STRIDE;   // 17160
constexpr int QS_OFF  = WS2_OFF + 48 * WS2_STRIDE;  // 41928
constexpr int KT_OFF  = QS_OFF  + 66 * QS_STRIDE;   // 44304
constexpr int VS_OFF  = KT_OFF  + 32 * KT_STRIDE;   // 46480
constexpr int PP_OFF  = VS_OFF  + 68 * VS_STRIDE;   // 48792
constexpr int OO_OFF  = PP_OFF  + 66 * PP_STRIDE;   // 53280
constexpr int WC_OFF  = OO_OFF  + 68 * OO_STRIDE;   // 55524
constexpr int SMEM_FLOATS = WC_OFF + 22 * WC_STRIDE; // 57020 -> 228080 B

typedef unsigned long long ull;

// pre-paired weights: Wpk[h][p][k] = (Wcol(2p)[k], Wcol(2p+1)[k]), cols 0..95 = q|k|v
__device__ float2 g_Wpk[8 * 48 * 256];

__global__ void repack_weights(const float* __restrict__ Wq,
                               const float* __restrict__ Wk,
                               const float* __restrict__ Wv) {
    int i = blockIdx.x * blockDim.x + threadIdx.x;
    if (i >= 8 * 48 * 256) return;
    int k = i & 255;
    int p = (i >> 8) % 48;
    int h = i / (48 * 256);
    int n0 = 2 * p, n1 = 2 * p + 1;
    const float* W0 = (n0 < 32) ? Wq : (n0 < 64 ? Wk : Wv);
    const float* W1 = (n1 < 32) ? Wq : (n1 < 64 ? Wk : Wv);
    g_Wpk[i] = make_float2(W0[(h * 32 + (n0 & 31)) * 256 + k],
                           W1[(h * 32 + (n1 & 31)) * 256 + k]);
}

static __device__ __forceinline__ ull pk2(float a, float b) {
    ull r; asm("mov.b64 %0, {%1,%2};" : "=l"(r) : "f"(a), "f"(b)); return r;
}
static __device__ __forceinline__ void upk2(ull v, float &a, float &b) {
    asm("mov.b64 {%0,%1}, %2;" : "=f"(a), "=f"(b) : "l"(v));
}
static __device__ __forceinline__ ull ffma2(ull a, ull b, ull c) {
    ull d; asm("fma.rn.f32x2 %0, %1, %2, %3;" : "=l"(d) : "l"(a), "l"(b), "l"(c)); return d;
}
static __device__ __forceinline__ void cp16(unsigned int dst, const void* src) {
    asm volatile("cp.async.ca.shared.global [%0], [%1], 16;" :: "r"(dst), "l"(src));
}
static __device__ __forceinline__ void cp_commit() { asm volatile("cp.async.commit_group;"); }
static __device__ __forceinline__ void cp_wait0()  { asm volatile("cp.async.wait_group 0;"); }

__global__ __launch_bounds__(512, 1)
void mha_fused_kernel(const float* __restrict__ x,
                      const float* __restrict__ bq,
                      const float* __restrict__ bk,
                      const float* __restrict__ bv,
                      const float* __restrict__ Wc, const float* __restrict__ bc,
                      float* __restrict__ out)
{
    extern __shared__ float sm[];
    float* xs  = sm + XS_OFF;
    float* ws2 = sm + WS2_OFF;
    float* qs  = sm + QS_OFF;
    float* kt  = sm + KT_OFF;
    float* vs  = sm + VS_OFF;
    float* pp  = sm + PP_OFF;
    float* oo  = sm + OO_OFF;
    float* wcs = sm + WC_OFF;

    const int bt   = blockIdx.x;
    const int tid  = threadIdx.x;
    const int lane = tid & 31;
    const int wid  = tid >> 5;
    const int tm   = lane;

    const unsigned int sbase = (unsigned int)__cvta_generic_to_shared(sm);

    // ---- stage x via cp.async (66 rows x 64 chunks of 16B) ----
    const float* xg = x + (size_t)bt * (Sn * 256);
    for (int c = tid; c < 66 * 64; c += 512) {
        int row = c >> 6, ch = c & 63;
        cp16(sbase + (unsigned)(XS_OFF + row * XS_STRIDE + ch * 4) * 4,
             xg + row * 256 + ch * 4);
    }
    // ---- stage ws2 for head 0 (48 rows x 128 chunks of 16B) ----
    {
        const float2* src = g_Wpk;  // h = 0
        for (int c = tid; c < 48 * 128; c += 512) {
            int row = c >> 7, ch = c & 127;
            cp16(sbase + (unsigned)(WS2_OFF + row * WS2_STRIDE + ch * 4) * 4,
                 src + row * 256 + ch * 2);
        }
    }
    cp_commit();

    // ---- stage wcs (+zero pads) and zero pad regions ----
    for (int idx = tid; idx < 22 * 68; idx += 512) {
        int j = idx / 68, c = idx - j * 68;
        wcs[idx] = (c < 66) ? Wc[j * 66 + c] : 0.0f;
    }
    if (tid < 132) {                      // pp pad cols 66,67
        int i = tid >> 1;
        pp[i * PP_STRIDE + 66 + (tid & 1)] = 0.0f;
    } else if (tid < 200) {               // vs pad rows 66,67 (68 floats)
        vs[66 * VS_STRIDE + (tid - 132)] = 0.0f;
    } else if (tid < 266) {               // oo pad rows 66,67 (66 floats)
        oo[66 * OO_STRIDE + (tid - 200)] = 0.0f;
    }

    const float scale = 0.17677669529663687f; // 1/sqrt(32)

    for (int h = 0; h < Hh; ++h) {
        cp_wait0();
        __syncthreads();   // ws2[h] (and x on h=0) visible to all

        // ================= QKV projection =================
        if (wid < 12) {
            // rows {tm, tm+32}, pairs p0..p0+3 (cols 2p0..2p0+7)
            const int p0 = wid * 4;
            ull acc[2][4];
            #pragma unroll
            for (int u = 0; u < 2; ++u)
                #pragma unroll
                for (int j = 0; j < 4; ++j) acc[u][j] = 0ULL;

            const float4* xa0 = reinterpret_cast<const float4*>(xs + tm * XS_STRIDE);
            const float4* xa1 = reinterpret_cast<const float4*>(xs + (tm + 32) * XS_STRIDE);
            const longlong2* w0 = reinterpret_cast<const longlong2*>(ws2 + (p0 + 0) * WS2_STRIDE);
            const longlong2* w1 = reinterpret_cast<const longlong2*>(ws2 + (p0 + 1) * WS2_STRIDE);
            const longlong2* w2 = reinterpret_cast<const longlong2*>(ws2 + (p0 + 2) * WS2_STRIDE);
            const longlong2* w3 = reinterpret_cast<const longlong2*>(ws2 + (p0 + 3) * WS2_STRIDE);

            #pragma unroll 2
            for (int kc = 0; kc < 64; ++kc) {
                float4 a0 = xa0[kc], a1 = xa1[kc];
                longlong2 b0l = w0[2 * kc], b0h = w0[2 * kc + 1];
                longlong2 b1l = w1[2 * kc], b1h = w1[2 * kc + 1];
                longlong2 b2l = w2[2 * kc], b2h = w2[2 * kc + 1];
                longlong2 b3l = w3[2 * kc], b3h = w3[2 * kc + 1];
                float a0a[4] = {a0.x, a0.y, a0.z, a0.w};
                float a1a[4] = {a1.x, a1.y, a1.z, a1.w};
                ull bb[4][4] = {
                    {(ull)b0l.x, (ull)b0l.y, (ull)b0h.x, (ull)b0h.y},
                    {(ull)b1l.x, (ull)b1l.y, (ull)b1h.x, (ull)b1h.y},
                    {(ull)b2l.x, (ull)b2l.y, (ull)b2h.x, (ull)b2h.y},
                    {(ull)b3l.x, (ull)b3l.y, (ull)b3h.x, (ull)b3h.y}};
                #pragma unroll
                for (int kk = 0; kk < 4; ++kk) {
                    ull u0 = pk2(a0a[kk], a0a[kk]);
                    ull u1 = pk2(a1a[kk], a1a[kk]);
                    #pragma unroll
                    for (int jp = 0; jp < 4; ++jp) {
                        acc[0][jp] = ffma2(u0, bb[jp][kk], acc[0][jp]);
                        acc[1][jp] = ffma2(u1, bb[jp][kk], acc[1][jp]);
                    }
                }
            }

            #pragma unroll
            for (int u = 0; u < 2; ++u) {
                int r = tm + 32 * u;
                #pragma unroll
                for (int jp = 0; jp < 4; ++jp) {
                    float vlo, vhi;
                    upk2(acc[u][jp], vlo, vhi);
                    int n = 2 * (p0 + jp);
                    #pragma unroll
                    for (int e = 0; e < 2; ++e) {
                        int nn = n + e;
                        float val = (e == 0) ? vlo : vhi;
                        const float* bsrc = (nn < 32) ? bq : (nn < 64 ? bk : bv);
                        val += bsrc[h * 32 + (nn & 31)];
                        if (nn < 32)      qs[r * QS_STRIDE + nn] = val;
                        else if (nn < 64) kt[(nn - 32) * KT_STRIDE + r] = val;
                        else              vs[r * VS_STRIDE + (nn - 64)] = fmaxf(val, 0.0f);
                    }
                }
            }
        } else if (tid < 480) {
            // cleanup rows 64,65: 96 threads, one pair each, full k
            int t2 = tid - 384;
            int row = 64 + t2 / 48;
            int p = t2 % 48;
            const float4* xa = reinterpret_cast<const float4*>(xs + row * XS_STRIDE);
            const ull* wr = reinterpret_cast<const ull*>(ws2 + p * WS2_STRIDE);
            ull acc = 0ULL;
            #pragma unroll 4
            for (int kc = 0; kc < 64; ++kc) {
                float4 a = xa[kc];
                acc = ffma2(pk2(a.x, a.x), wr[4 * kc + 0], acc);
                acc = ffma2(pk2(a.y, a.y), wr[4 * kc + 1], acc);
                acc = ffma2(pk2(a.z, a.z), wr[4 * kc + 2], acc);
                acc = ffma2(pk2(a.w, a.w), wr[4 * kc + 3], acc);
            }
            float v0, v1;
            upk2(acc, v0, v1);
            #pragma unroll
            for (int e = 0; e < 2; ++e) {
                int nn = 2 * p + e;
                float val = (e == 0) ? v0 : v1;
                const float* bsrc = (nn < 32) ? bq : (nn < 64 ? bk : bv);
                val += bsrc[h * 32 + (nn & 31)];
                if (nn < 32)      qs[row * QS_STRIDE + nn] = val;
                else if (nn < 64) kt[(nn - 32) * KT_STRIDE + row] = val;
                else              vs[row * VS_STRIDE + (nn - 64)] = fmaxf(val, 0.0f);
            }
        }
        __syncthreads();

        // prefetch next head's weights (hidden behind attention phases)
        if (h + 1 < Hh) {
            const float2* src = g_Wpk + (size_t)(h + 1) * (48 * 256);
            for (int c = tid; c < 48 * 128; c += 512) {
                int row = c >> 7, ch = c & 127;
                cp16(sbase + (unsigned)(WS2_OFF + row * WS2_STRIDE + ch * 4) * 4,
                     src + row * 256 + ch * 2);
            }
            cp_commit();
        }

        // ================= scores =================
        {
            int j0 = wid * 4;   // 16 warps x 4 cols = 64
            ull acc[2][2] = {{0ULL, 0ULL}, {0ULL, 0ULL}};
            const float4* qa0 = reinterpret_cast<const float4*>(qs + tm * QS_STRIDE);
            const float4* qa1 = reinterpret_cast<const float4*>(qs + (tm + 32) * QS_STRIDE);
            #pragma unroll
            for (int dc = 0; dc < 8; ++dc) {
                float4 q0 = qa0[dc], q1 = qa1[dc];
                float q0a[4] = {q0.x, q0.y, q0.z, q0.w};
                float q1a[4] = {q1.x, q1.y, q1.z, q1.w};
                #pragma unroll
                for (int dd = 0; dd < 4; ++dd) {
                    longlong2 bt2 = *reinterpret_cast<const longlong2*>(
                        kt + (4 * dc + dd) * KT_STRIDE + j0);
                    ull u0 = pk2(q0a[dd], q0a[dd]);
                    ull u1 = pk2(q1a[dd], q1a[dd]);
                    acc[0][0] = ffma2(u0, (ull)bt2.x, acc[0][0]);
                    acc[0][1] = ffma2(u0, (ull)bt2.y, acc[0][1]);
                    acc[1][0] = ffma2(u1, (ull)bt2.x, acc[1][0]);
                    acc[1][1] = ffma2(u1, (ull)bt2.y, acc[1][1]);
                }
            }
            #pragma unroll
            for (int u = 0; u < 2; ++u) {
                int i = tm + 32 * u;
                #pragma unroll
                for (int jp = 0; jp < 2; ++jp) {
                    float s0, s1;
                    upk2(acc[u][jp], s0, s1);
                    int j = j0 + 2 * jp;
                    bool m0 = (i < Jn && j     >= 2 * Jn) || (i >= 2 * Jn && j     < Jn);
                    bool m1 = (i < Jn && j + 1 >= 2 * Jn) || (i >= 2 * Jn && j + 1 < Jn);
                    pp[i * PP_STRIDE + j]     = m0 ? 0.0f : s0 * scale;
                    pp[i * PP_STRIDE + j + 1] = m1 ? 0.0f : s1 * scale;
                }
            }
        }
        if (tid < 260) {   // rows 64,65 all j; cols 64,65 for i<64
            int i, j;
            if (tid < 132) { i = 64 + tid / 66; j = tid % 66; }
            else { int t2 = tid - 132; i = t2 >> 1; j = 64 + (t2 & 1); }
            bool masked = (i < Jn && j >= 2 * Jn) || (i >= 2 * Jn && j < Jn);
            float s = 0.0f;
            if (!masked) {
                const float* qi = qs + i * QS_STRIDE;
                float d0 = 0.0f;
                #pragma unroll 8
                for (int d = 0; d < 32; ++d) d0 += qi[d] * kt[d * KT_STRIDE + j];
                s = d0 * scale;
            }
            pp[i * PP_STRIDE + j] = s;
        }
        __syncthreads();

        // ================= softmax with threshold pruning =================
        for (int r = wid; r < Sn; r += 16) {
            float* row = pp + r * PP_STRIDE;
            float v0 = row[lane];
            float v1 = row[lane + 32];
            float v2 = (lane < 2) ? row[lane + 64] : -FLT_MAX;
            float m = fmaxf(fmaxf(v0, v1), v2);
            #pragma unroll
            for (int o = 16; o; o >>= 1) m = fmaxf(m, __shfl_xor_sync(0xffffffffu, m, o));
            float thr = m * (1.0f / 9.0f);
            float t0 = (fabsf(v0) <= thr) ? NEGV : v0;
            float t1 = (fabsf(v1) <= thr) ? NEGV : v1;
            float t2v = (lane < 2) ? ((fabsf(v2) <= thr) ? NEGV : v2) : -FLT_MAX;
            float M2 = fmaxf(fmaxf(t0, t1), t2v);
            #pragma unroll
            for (int o = 16; o; o >>= 1) M2 = fmaxf(M2, __shfl_xor_sync(0xffffffffu, M2, o));
            float e0 = __expf(t0 - M2);
            float e1 = __expf(t1 - M2);
            float e2 = (lane < 2) ? __expf(t2v - M2) : 0.0f;
            float s = e0 + e1 + e2;
            #pragma unroll
            for (int o = 16; o; o >>= 1) s += __shfl_xor_sync(0xffffffffu, s, o);
            float inv = 1.0f / s;
            row[lane]      = e0 * inv;
            row[lane + 32] = e1 * inv;
            if (lane < 2) row[lane + 64] = e2 * inv;
        }
        __syncthreads();

        // ================= P @ V =================
        {
            int dd0 = wid * 2;
            ull acc0 = 0ULL, acc1 = 0ULL;
            const float4* pa0 = reinterpret_cast<const float4*>(pp + tm * PP_STRIDE);
            const float4* pa1 = reinterpret_cast<const float4*>(pp + (tm + 32) * PP_STRIDE);
            #pragma unroll 4
            for (int cc = 0; cc < 17; ++cc) {
                float4 p0 = pa0[cc], p1 = pa1[cc];
                float p0a[4] = {p0.x, p0.y, p0.z, p0.w};
                float p1a[4] = {p1.x, p1.y, p1.z, p1.w};
                #pragma unroll
                for (int c = 0; c < 4; ++c) {
                    ull bv2 = *reinterpret_cast<const ull*>(vs + (4 * cc + c) * VS_STRIDE + dd0);
                    acc0 = ffma2(pk2(p0a[c], p0a[c]), bv2, acc0);
                    acc1 = ffma2(pk2(p1a[c], p1a[c]), bv2, acc1);
                }
            }
            float r00, r01, r10, r11;
            upk2(acc0, r00, r01);
            upk2(acc1, r10, r11);
            oo[tm * OO_STRIDE + dd0]            = r00;
            oo[tm * OO_STRIDE + dd0 + 1]        = r01;
            oo[(tm + 32) * OO_STRIDE + dd0]     = r10;
            oo[(tm + 32) * OO_STRIDE + dd0 + 1] = r11;
        }
        if (tid < 64) {   // rows 64,65
            int row = 64 + (tid >= 32);
            int dd = tid & 31;
            const float* pr = pp + row * PP_STRIDE;
            float a = 0.0f;
            #pragma unroll 6
            for (int c = 0; c < Sn; ++c) a += pr[c] * vs[c * VS_STRIDE + dd];
            oo[row * OO_STRIDE + dd] = a;
        }
        __syncthreads();

        // ================= classifier + output =================
        const size_t obase = (size_t)bt * (Jn * 256) + (size_t)h * 32;
        for (int t = tid; t < Jn * 32; t += 512) {
            int j = t >> 5, dd = t & 31;
            const float4* wr = reinterpret_cast<const float4*>(wcs + j * WC_STRIDE);
            float a = bc[j];
            #pragma unroll
            for (int cc = 0; cc < 17; ++cc) {
                float4 w = wr[cc];
                const float* ob = oo + (4 * cc) * OO_STRIDE + dd;
                a += w.x * ob[0] + w.y * ob[OO_STRIDE]
                   + w.z * ob[2 * OO_STRIDE] + w.w * ob[3 * OO_STRIDE];
            }
            out[obase + (size_t)j * 256 + dd] = a;
        }
        __syncthreads();
    }
}

extern "C" void kernel_launch(void* const* d_in, const int* in_sizes, int n_in,
                              void* d_out, int out_size) {
    const float* x  = (const float*)d_in[0];
    const float* Wq = (const float*)d_in[1];
    const float* bq = (const float*)d_in[2];
    const float* Wk = (const float*)d_in[3];
    const float* bk = (const float*)d_in[4];
    const float* Wv = (const float*)d_in[5];
    const float* bv = (const float*)d_in[6];
    const float* Wc = (const float*)d_in[7];
    const float* bc = (const float*)d_in[8];
    float* out = (float*)d_out;

    repack_weights<<<(8 * 48 * 256 + 255) / 256, 256>>>(Wq, Wk, Wv);

    int blocks = in_sizes[0] / (Sn * 256);   // B*T = 3072
    size_t smem = (size_t)SMEM_FLOATS * sizeof(float);  // 228080 B
    cudaFuncSetAttribute(mha_fused_kernel,
                         cudaFuncAttributeMaxDynamicSharedMemorySize, (int)smem);
    mha_fused_kernel<<<blocks, 512, smem>>>(x, bq, bk, bv, Wc, bc, out);
}